// round 12
// baseline (speedup 1.0000x reference)
#include <cuda_runtime.h>
#include <cuda_bf16.h>
#include <cstdint>

// ============================================================================
// BinaryLinearWscales (GB300). Dual-pipe hybrid, rebalanced f=0.5:
//   tensor pipe (255 MAC/cyc/SM): level-1 q1 x sign, N cols 0..31  (mma.sync)
//   fma pipe    (512 MAC/cyc/SM): level-2 q2 x sign, all 64 cols   (dp4a)
//                               + level-1 q1 x sign, N cols 32..63 (dp4a)
//   x ~= alpha_m * (q1 + q2/254), sign(W) exact in s8.
// dp4a thread tile 2 rows x 8 cols (halves duplicated A smem traffic).
// ============================================================================

// ---------------- device scratch (pre-swizzled tiled s8) --------------------
__device__ __align__(16384) int8_t g_a0[16777216];   // 16 MB: q1 of x
__device__ __align__(16384) int8_t g_a1[16777216];   // 16 MB: q2 of x
__device__ __align__(16384) int8_t g_b [16777216];   // 16 MB: sign(W)
__device__ float g_scale [4096];
__device__ float g_rowsum[4096];

// ---------------- PTX helpers ------------------------------------------------
static __device__ __forceinline__ uint32_t smem_u32(const void* p) {
    uint32_t a;
    asm("{ .reg .u64 t; cvta.to.shared.u64 t, %1; cvt.u32.u64 %0, t; }" : "=r"(a) : "l"(p));
    return a;
}

#define MBARRIER_INIT(addr, cnt) \
    asm volatile("mbarrier.init.shared.b64 [%0], %1;" :: "r"((uint32_t)(addr)), "r"((uint32_t)(cnt)) : "memory")

#define MBARRIER_EXPECT_TX(addr, bytes) \
    asm volatile("mbarrier.arrive.expect_tx.shared.b64 _, [%0], %1;" :: "r"((uint32_t)(addr)), "r"((uint32_t)(bytes)) : "memory")

#define MBARRIER_ARRIVE(addr) \
    asm volatile("mbarrier.arrive.shared.b64 _, [%0];" :: "r"((uint32_t)(addr)) : "memory")

#define MBARRIER_WAIT_PARITY(mbar_addr, parity) do {                               \
    uint32_t _m = (uint32_t)(mbar_addr); uint32_t _p = (uint32_t)(parity);         \
    uint32_t _d;                                                                    \
    asm volatile("{\n\t.reg .pred p;\n\t"                                           \
        "mbarrier.try_wait.parity.acquire.cta.shared::cta.b64 p, [%1], %2;\n\t"     \
        "selp.b32 %0, 1, 0, p;\n\t}" : "=r"(_d) : "r"(_m), "r"(_p) : "memory");     \
    if (!_d) {                                                                      \
        asm volatile("{\n\t.reg .pred P1;\n\t"                                      \
        "WL_%=:\n\t"                                                                \
        "mbarrier.try_wait.parity.acquire.cta.shared::cta.b64 P1, [%0], %1, 0x989680;\n\t" \
        "@P1 bra.uni WD_%=;\n\t"                                                    \
        "bra.uni WL_%=;\n\t"                                                        \
        "WD_%=:\n\t}" :: "r"(_m), "r"(_p) : "memory");                              \
    }                                                                               \
} while (0)

#define MBARRIER_WAIT_PARITY_RELAXED(mbar_addr, parity) do {                       \
    uint32_t _m = (uint32_t)(mbar_addr); uint32_t _p = (uint32_t)(parity);         \
    uint32_t _d;                                                                    \
    asm volatile("{\n\t.reg .pred p;\n\t"                                           \
        "mbarrier.try_wait.parity.relaxed.cta.shared::cta.b64 p, [%1], %2, 0x989680;\n\t" \
        "selp.b32 %0, 1, 0, p;\n\t}" : "=r"(_d) : "r"(_m), "r"(_p) : "memory");     \
    if (!_d) {                                                                      \
        asm volatile("{\n\t.reg .pred P1;\n\t"                                      \
        "WL_%=:\n\t"                                                                \
        "mbarrier.try_wait.parity.relaxed.cta.shared::cta.b64 P1, [%0], %1, 0x989680;\n\t" \
        "@P1 bra.uni WD_%=;\n\t"                                                    \
        "bra.uni WL_%=;\n\t"                                                        \
        "WD_%=:\n\t}" :: "r"(_m), "r"(_p) : "memory");                              \
    }                                                                               \
} while (0)

static __device__ __forceinline__ void bulk_g2s(uint32_t dst, const void* src,
                                                uint32_t bytes, uint32_t mbar) {
    asm volatile(
        "cp.async.bulk.shared::cluster.global.mbarrier::complete_tx::bytes [%0], [%1], %2, [%3];"
        :: "r"(dst), "l"(src), "r"(bytes), "r"(mbar) : "memory");
}

static __device__ __forceinline__ void ldsm4(uint32_t* r, uint32_t addr) {
    asm volatile("ldmatrix.sync.aligned.m8n8.x4.shared.b16 {%0,%1,%2,%3}, [%4];"
        : "=r"(r[0]), "=r"(r[1]), "=r"(r[2]), "=r"(r[3]) : "r"(addr));
}

static __device__ __forceinline__ void ldsm2(uint32_t* r, uint32_t addr) {
    asm volatile("ldmatrix.sync.aligned.m8n8.x2.shared.b16 {%0,%1}, [%2];"
        : "=r"(r[0]), "=r"(r[1]) : "r"(addr));
}

static __device__ __forceinline__ void imma(int* d, const uint32_t* a,
                                            uint32_t b0, uint32_t b1) {
    asm volatile(
        "mma.sync.aligned.m16n8k32.row.col.s32.s8.s8.s32 "
        "{%0,%1,%2,%3}, {%4,%5,%6,%7}, {%8,%9}, {%0,%1,%2,%3};"
        : "+r"(d[0]), "+r"(d[1]), "+r"(d[2]), "+r"(d[3])
        : "r"(a[0]), "r"(a[1]), "r"(a[2]), "r"(a[3]), "r"(b0), "r"(b1));
}

static __device__ __forceinline__ void dp4x4(int* acc, const int4& a, const int4& b) {
    *acc = __dp4a(a.x, b.x, *acc);
    *acc = __dp4a(a.y, b.y, *acc);
    *acc = __dp4a(a.z, b.z, *acc);
    *acc = __dp4a(a.w, b.w, *acc);
}

// ---------------- geometry ----------------------------------------------------
static constexpr int      NCHUNK      = 32;       // 4096 / 128
static constexpr uint32_t TILE_BYTES  = 16384;    // 128 rows x 128 k-bytes
static constexpr uint32_t BTILE_BYTES = 8192;     // 64 rows x 128 k-bytes
static constexpr int      STAGES      = 4;
static constexpr uint32_t OFF_A1      = 16384;
static constexpr uint32_t OFF_B       = 32768;
static constexpr uint32_t STAGE_BYTES = 40960;    // A0 16K + A1 16K + B 8K
static constexpr uint32_t OFF_FULL    = 0;
static constexpr uint32_t OFF_EMPTY   = 64;
static constexpr uint32_t OFF_STAGE   = 1024;
static constexpr uint32_t SMEM_DYN    = OFF_STAGE + STAGES * STAGE_BYTES;  // 164864

// ---------------- merged prologue: pack x (y=0) and sign(W) (y=1) ------------
__global__ void __launch_bounds__(256) prep_kernel(const float* __restrict__ x,
                                                   const float* __restrict__ w) {
    const int row = blockIdx.x;
    const int tid = threadIdx.x;
    const bool is_x = (blockIdx.y == 0);
    const float* src = (is_x ? x : w) + (size_t)row * 4096;

    float4 v[4];
    #pragma unroll
    for (int i = 0; i < 4; i++) v[i] = ((const float4*)src)[tid * 4 + i];

    const uint32_t inrow = (uint32_t)((tid & 7) * 16);
    const uint32_t swzc  = inrow ^ (uint32_t)((row & 7) << 4);
    const size_t off = ((size_t)(row >> 7) * 32 + (size_t)(tid >> 3)) * TILE_BYTES
                     + (size_t)((row & 127) * 128) + swzc;

    if (is_x) {
        float mx = 0.f, sm = 0.f;
        #pragma unroll
        for (int i = 0; i < 4; i++) {
            mx = fmaxf(mx, fmaxf(fmaxf(fabsf(v[i].x), fabsf(v[i].y)),
                                 fmaxf(fabsf(v[i].z), fabsf(v[i].w))));
            sm += (v[i].x + v[i].y) + (v[i].z + v[i].w);
        }
        __shared__ float smax[256], ssum[256];
        smax[tid] = mx; ssum[tid] = sm;
        __syncthreads();
        for (int s = 128; s > 0; s >>= 1) {
            if (tid < s) {
                smax[tid] = fmaxf(smax[tid], smax[tid + s]);
                ssum[tid] += ssum[tid + s];
            }
            __syncthreads();
        }
        const float maxv = smax[0];
        const float inv  = (maxv > 0.f) ? 127.f / maxv : 0.f;

        uint32_t p1[4], p2[4];
        #pragma unroll
        for (int i = 0; i < 4; i++) {
            float e[4] = {v[i].x, v[i].y, v[i].z, v[i].w};
            uint32_t w1 = 0, w2 = 0;
            #pragma unroll
            for (int b = 0; b < 4; b++) {
                float r0 = e[b] * inv;
                int q1 = __float2int_rn(r0);
                int q2 = __float2int_rn((r0 - (float)q1) * 254.f);
                w1 |= (uint32_t)(q1 & 0xff) << (8 * b);
                w2 |= (uint32_t)(q2 & 0xff) << (8 * b);
            }
            p1[i] = w1; p2[i] = w2;
        }
        *(uint4*)((char*)g_a0 + off) = make_uint4(p1[0], p1[1], p1[2], p1[3]);
        *(uint4*)((char*)g_a1 + off) = make_uint4(p2[0], p2[1], p2[2], p2[3]);
        if (tid == 0) {
            g_scale[row]  = (maxv > 0.f) ? maxv / 127.f : 0.f;
            g_rowsum[row] = ssum[0];
        }
    } else {
        uint32_t p[4];
        #pragma unroll
        for (int i = 0; i < 4; i++) {
            float e[4] = {v[i].x, v[i].y, v[i].z, v[i].w};
            uint32_t wq = 0;
            #pragma unroll
            for (int b = 0; b < 4; b++) {
                int q = (e[b] > 0.f) ? 1 : ((e[b] < 0.f) ? -1 : 0);
                wq |= (uint32_t)(q & 0xff) << (8 * b);
            }
            p[i] = wq;
        }
        *(uint4*)((char*)g_b + off) = make_uint4(p[0], p[1], p[2], p[3]);
    }
}

// ---------------- main GEMM ----------------------------------------------------
// grid (64 ntile, 32 mtile), 512 threads. CTA tile 128M x 64N.
// mma: 16 warps 4Mx4N, warp tile 32x8, cols 0..31.
// dp4a: thread (g=tid&63, h=tid>>6): rows {g, g+64};
//   level-2 cols {h+8j, j=0..7}; level-1p cols {h+8j, j=4..7} (i.e. 32..63).
__global__ void __launch_bounds__(512, 1)
gemm_kernel(const float* __restrict__ wscale, const float* __restrict__ wbias,
            float* __restrict__ out) {
    extern __shared__ __align__(1024) char smem[];
    const uint32_t sb = smem_u32(smem);
    const int tid = threadIdx.x;
    const int wid = tid >> 5;
    const int lane = tid & 31;
    const int ntile = blockIdx.x;   // 0..63
    const int mtile = blockIdx.y;   // 0..31

    const char* pa0 = (const char*)g_a0 + (size_t)mtile * (32u * TILE_BYTES);
    const char* pa1 = (const char*)g_a1 + (size_t)mtile * (32u * TILE_BYTES);
    const char* pb  = (const char*)g_b  + (size_t)(ntile >> 1) * (32u * TILE_BYTES)
                    + (size_t)(ntile & 1) * BTILE_BYTES;

    if (tid == 0) {
        #pragma unroll
        for (int s = 0; s < STAGES; s++) {
            MBARRIER_INIT(sb + OFF_FULL  + 8u * s, 1);
            MBARRIER_INIT(sb + OFF_EMPTY + 8u * s, 16);
        }
    }
    __syncthreads();

    if (tid == 0) {
        #pragma unroll
        for (int s = 0; s < STAGES; s++) {
            uint32_t fb = sb + OFF_FULL + 8u * s;
            MBARRIER_EXPECT_TX(fb, STAGE_BYTES);
            uint32_t dst = sb + OFF_STAGE + (uint32_t)s * STAGE_BYTES;
            size_t co = (size_t)s * TILE_BYTES;
            bulk_g2s(dst,          pa0 + co, TILE_BYTES,  fb);
            bulk_g2s(dst + OFF_A1, pa1 + co, TILE_BYTES,  fb);
            bulk_g2s(dst + OFF_B,  pb  + co, BTILE_BYTES, fb);
        }
    }

    // ---- mma tiling: 4(M) x 4(N) warps, warp tile 32x8, cols 0..31 ----
    const int mw = wid >> 2;          // 0..3
    const int nw = wid & 3;           // 0..3
    const int rA = lane & 15;
    const uint32_t hbA = (uint32_t)((lane >> 4) * 16);
    const uint32_t phA = (uint32_t)((rA & 7) << 4);

    uint32_t rowA[2];
    #pragma unroll
    for (int t = 0; t < 2; t++) rowA[t] = (uint32_t)((mw * 32 + t * 16 + rA) * 128);
    // B ldsm.x2: lanes 0..15: row nw*8 + (lane&7), 16B col (lane>>3)&1
    const uint32_t rowBb = (uint32_t)((nw * 8 + (lane & 7)) * 128);
    const uint32_t hbB   = (uint32_t)(((lane >> 3) & 1) * 16);
    const uint32_t phB   = (uint32_t)((lane & 7) << 4);

    // ---- dp4a tiling ----
    const int g = tid & 63;           // row base (rows g, g+64)
    const int h = tid >> 6;           // 0..7 col base
    const uint32_t aswz = (uint32_t)((g & 7) * 16);
    const uint32_t bswz = (uint32_t)(h << 4);      // all b rows have row&7 == h

    int acc0[2][4];                   // mma accumulators (8 regs)
    int accL[2][8];                   // level-2 dp4a (16 regs)
    int accP[2][4];                   // level-1p dp4a (8 regs)
    #pragma unroll
    for (int t = 0; t < 2; t++) {
        #pragma unroll
        for (int i = 0; i < 4; i++) { acc0[t][i] = 0; accP[t][i] = 0; }
        #pragma unroll
        for (int j = 0; j < 8; j++) accL[t][j] = 0;
    }

    for (int ch = 0; ch < NCHUNK; ch++) {
        const int st = ch & 3;
        const int ph = (ch >> 2) & 1;
        MBARRIER_WAIT_PARITY(sb + OFF_FULL + 8u * st, ph);
        const uint32_t SA0 = sb + OFF_STAGE + (uint32_t)st * STAGE_BYTES;
        const uint32_t SB  = SA0 + OFF_B;
        const char* cSA0 = smem + OFF_STAGE + (uint32_t)st * STAGE_BYTES;
        const char* cSA1 = cSA0 + OFF_A1;
        const char* cSB  = cSA0 + OFF_B;

        #pragma unroll
        for (int ks = 0; ks < 4; ks++) {
            // ---- tensor pipe: level-1 mma, cols 0..31 (2 imma) ----
            {
                uint32_t a0f[2][4], bf[2];
                const uint32_t colA = (((uint32_t)(ks * 32)) + hbA) ^ phA;
                ldsm4(a0f[0], SA0 + rowA[0] + colA);
                ldsm4(a0f[1], SA0 + rowA[1] + colA);
                ldsm2(bf, SB + rowBb + ((((uint32_t)(ks * 32)) + hbB) ^ phB));
                imma(acc0[0], a0f[0], bf[0], bf[1]);
                imma(acc0[1], a0f[1], bf[0], bf[1]);
            }

            // ---- fma pipe: dp4a level-2 (all cols) + level-1p (cols 32..63) --
            #pragma unroll
            for (int sub = 0; sub < 2; sub++) {
                const uint32_t col = (uint32_t)(ks * 32 + sub * 16);
                const uint32_t ca = col ^ aswz;
                const uint32_t cb = col ^ bswz;
                const int4 a1r0 = *(const int4*)(cSA1 + g * 128 + ca);
                const int4 a1r1 = *(const int4*)(cSA1 + (g + 64) * 128 + ca);
                const int4 a0r0 = *(const int4*)(cSA0 + g * 128 + ca);
                const int4 a0r1 = *(const int4*)(cSA0 + (g + 64) * 128 + ca);
                #pragma unroll
                for (int jp = 0; jp < 4; jp++) {
                    const int rb = h + 16 * jp;
                    const int4 b0 = *(const int4*)(cSB + rb * 128 + cb);
                    const int4 b1 = *(const int4*)(cSB + (rb + 8) * 128 + cb);
                    dp4x4(&accL[0][2 * jp],     a1r0, b0);
                    dp4x4(&accL[0][2 * jp + 1], a1r0, b1);
                    dp4x4(&accL[1][2 * jp],     a1r1, b0);
                    dp4x4(&accL[1][2 * jp + 1], a1r1, b1);
                    if (jp >= 2) {
                        const int jj = jp - 2;
                        dp4x4(&accP[0][2 * jj],     a0r0, b0);
                        dp4x4(&accP[0][2 * jj + 1], a0r0, b1);
                        dp4x4(&accP[1][2 * jj],     a0r1, b0);
                        dp4x4(&accP[1][2 * jj + 1], a0r1, b1);
                    }
                }
            }
        }
        if (lane == 0) MBARRIER_ARRIVE(sb + OFF_EMPTY + 8u * st);
        if (tid == 0 && ch + STAGES < NCHUNK) {
            MBARRIER_WAIT_PARITY_RELAXED(sb + OFF_EMPTY + 8u * st, ph);
            uint32_t fb = sb + OFF_FULL + 8u * st;
            MBARRIER_EXPECT_TX(fb, STAGE_BYTES);
            uint32_t dst = sb + OFF_STAGE + (uint32_t)st * STAGE_BYTES;
            size_t co = (size_t)(ch + STAGES) * TILE_BYTES;
            bulk_g2s(dst,          pa0 + co, TILE_BYTES,  fb);
            bulk_g2s(dst + OFF_A1, pa1 + co, TILE_BYTES,  fb);
            bulk_g2s(dst + OFF_B,  pb  + co, BTILE_BYTES, fb);
        }
    }

    // ---------------- epilogue: stage dp4a sums via SMEM, combine ----------------
    __syncthreads();                       // all warps done with stage buffers
    int* sL = (int*)smem;                  // 128 x 68 ints (level-2, all 64 cols)
    int* sP = (int*)(smem + 36864);        // 128 x 36 ints (level-1p, cols-32)
    #pragma unroll
    for (int t = 0; t < 2; t++) {
        const int row = g + 64 * t;
        #pragma unroll
        for (int j = 0; j < 8; j++)
            sL[row * 68 + h + 8 * j] = accL[t][j];
        #pragma unroll
        for (int idx = 0; idx < 4; idx++)
            sP[row * 36 + h + 8 * idx] = accP[t][idx];
    }
    __syncthreads();

    const float inv254 = 1.f / 254.f;
    const int lg = lane >> 2;           // 0..7
    const int lc = (lane & 3) * 2;      // 0,2,4,6
    const int nl0 = nw * 8 + lc;        // local n (cols 0..31)
    #pragma unroll
    for (int t = 0; t < 2; t++) {
        #pragma unroll
        for (int half = 0; half < 2; half++) {
            const int ml = mw * 32 + t * 16 + lg + half * 8;   // local m
            const int m  = mtile * 128 + ml;
            const float alpha = g_scale[m];
            const float rs    = g_rowsum[m];
            float* orow = out + (size_t)m * 4096 + ntile * 64;
            const int i0 = half * 2, i1 = half * 2 + 1;
            // cols nl0, nl0+1 (mma-provided level-1)
            {
                float v0 = (float)acc0[t][i0] + (float)sL[ml * 68 + nl0]     * inv254;
                float v1 = (float)acc0[t][i1] + (float)sL[ml * 68 + nl0 + 1] * inv254;
                const int n = ntile * 64 + nl0;
                float2 o;
                o.x = __ldg(wscale + n)     * (alpha * v0) + __ldg(wbias + n)     * rs;
                o.y = __ldg(wscale + n + 1) * (alpha * v1) + __ldg(wbias + n + 1) * rs;
                *(float2*)(orow + nl0) = o;
            }
            // cols nl0+32, nl0+33 (dp4a-provided level-1p)
            {
                float v0 = (float)sP[ml * 36 + nl0]     + (float)sL[ml * 68 + nl0 + 32] * inv254;
                float v1 = (float)sP[ml * 36 + nl0 + 1] + (float)sL[ml * 68 + nl0 + 33] * inv254;
                const int n = ntile * 64 + nl0 + 32;
                float2 o;
                o.x = __ldg(wscale + n)     * (alpha * v0) + __ldg(wbias + n)     * rs;
                o.y = __ldg(wscale + n + 1) * (alpha * v1) + __ldg(wbias + n + 1) * rs;
                *(float2*)(orow + nl0 + 32) = o;
            }
        }
    }
}

// ---------------- launch --------------------------------------------------------
extern "C" void kernel_launch(void* const* d_in, const int* in_sizes, int n_in,
                              void* d_out, int out_size) {
    (void)in_sizes; (void)n_in; (void)out_size;
    const float* x      = (const float*)d_in[0];   // [2,2048,4096]
    const float* weight = (const float*)d_in[1];   // [4096,4096]
    const float* wscale = (const float*)d_in[2];   // [4096,1]
    const float* wbias  = (const float*)d_in[3];   // [4096,1]
    float* out = (float*)d_out;

    cudaFuncSetAttribute(gemm_kernel, cudaFuncAttributeMaxDynamicSharedMemorySize,
                         (int)SMEM_DYN);

    prep_kernel<<<dim3(4096, 2), 256>>>(x, weight);
    gemm_kernel<<<dim3(64, 32), 512, SMEM_DYN>>>(wscale, wbias, out);
}

// round 13
// speedup vs baseline: 1.1569x; 1.1569x over previous
#include <cuda_runtime.h>
#include <cuda_bf16.h>
#include <cstdint>

// ============================================================================
// BinaryLinearWscales (GB300). Hybrid dual-pipe GEMM (R11 base, 1438us):
//   level-1 (q1): mma.sync m16n8k32.s8 -> tensor pipe
//   level-2 (q2): dp4a                 -> fma pipe
//   x ~= alpha_m * (q1 + q2/254), sign(W) exact in s8.
// R13: warp-parity phase stagger. Even warps: mma then dp4a per ks; odd
// warps: dp4a then mma. Keeps both pipes fed simultaneously (R11/R12 showed
// chunk time = tensor_busy + fma_busy, i.e. zero overlap from lockstep phases).
// ============================================================================

// ---------------- device scratch (pre-swizzled tiled s8) --------------------
__device__ __align__(16384) int8_t g_a0[16777216];   // 16 MB: q1 of x
__device__ __align__(16384) int8_t g_a1[16777216];   // 16 MB: q2 of x
__device__ __align__(16384) int8_t g_b [16777216];   // 16 MB: sign(W)
__device__ float g_scale [4096];
__device__ float g_rowsum[4096];

// ---------------- PTX helpers ------------------------------------------------
static __device__ __forceinline__ uint32_t smem_u32(const void* p) {
    uint32_t a;
    asm("{ .reg .u64 t; cvta.to.shared.u64 t, %1; cvt.u32.u64 %0, t; }" : "=r"(a) : "l"(p));
    return a;
}

#define MBARRIER_INIT(addr, cnt) \
    asm volatile("mbarrier.init.shared.b64 [%0], %1;" :: "r"((uint32_t)(addr)), "r"((uint32_t)(cnt)) : "memory")

#define MBARRIER_EXPECT_TX(addr, bytes) \
    asm volatile("mbarrier.arrive.expect_tx.shared.b64 _, [%0], %1;" :: "r"((uint32_t)(addr)), "r"((uint32_t)(bytes)) : "memory")

#define MBARRIER_ARRIVE(addr) \
    asm volatile("mbarrier.arrive.shared.b64 _, [%0];" :: "r"((uint32_t)(addr)) : "memory")

#define MBARRIER_WAIT_PARITY(mbar_addr, parity) do {                               \
    uint32_t _m = (uint32_t)(mbar_addr); uint32_t _p = (uint32_t)(parity);         \
    uint32_t _d;                                                                    \
    asm volatile("{\n\t.reg .pred p;\n\t"                                           \
        "mbarrier.try_wait.parity.acquire.cta.shared::cta.b64 p, [%1], %2;\n\t"     \
        "selp.b32 %0, 1, 0, p;\n\t}" : "=r"(_d) : "r"(_m), "r"(_p) : "memory");     \
    if (!_d) {                                                                      \
        asm volatile("{\n\t.reg .pred P1;\n\t"                                      \
        "WL_%=:\n\t"                                                                \
        "mbarrier.try_wait.parity.acquire.cta.shared::cta.b64 P1, [%0], %1, 0x989680;\n\t" \
        "@P1 bra.uni WD_%=;\n\t"                                                    \
        "bra.uni WL_%=;\n\t"                                                        \
        "WD_%=:\n\t}" :: "r"(_m), "r"(_p) : "memory");                              \
    }                                                                               \
} while (0)

#define MBARRIER_WAIT_PARITY_RELAXED(mbar_addr, parity) do {                       \
    uint32_t _m = (uint32_t)(mbar_addr); uint32_t _p = (uint32_t)(parity);         \
    uint32_t _d;                                                                    \
    asm volatile("{\n\t.reg .pred p;\n\t"                                           \
        "mbarrier.try_wait.parity.relaxed.cta.shared::cta.b64 p, [%1], %2, 0x989680;\n\t" \
        "selp.b32 %0, 1, 0, p;\n\t}" : "=r"(_d) : "r"(_m), "r"(_p) : "memory");     \
    if (!_d) {                                                                      \
        asm volatile("{\n\t.reg .pred P1;\n\t"                                      \
        "WL_%=:\n\t"                                                                \
        "mbarrier.try_wait.parity.relaxed.cta.shared::cta.b64 P1, [%0], %1, 0x989680;\n\t" \
        "@P1 bra.uni WD_%=;\n\t"                                                    \
        "bra.uni WL_%=;\n\t"                                                        \
        "WD_%=:\n\t}" :: "r"(_m), "r"(_p) : "memory");                              \
    }                                                                               \
} while (0)

static __device__ __forceinline__ void bulk_g2s(uint32_t dst, const void* src,
                                                uint32_t bytes, uint32_t mbar) {
    asm volatile(
        "cp.async.bulk.shared::cluster.global.mbarrier::complete_tx::bytes [%0], [%1], %2, [%3];"
        :: "r"(dst), "l"(src), "r"(bytes), "r"(mbar) : "memory");
}

static __device__ __forceinline__ void ldsm4(uint32_t* r, uint32_t addr) {
    asm volatile("ldmatrix.sync.aligned.m8n8.x4.shared.b16 {%0,%1,%2,%3}, [%4];"
        : "=r"(r[0]), "=r"(r[1]), "=r"(r[2]), "=r"(r[3]) : "r"(addr));
}

static __device__ __forceinline__ void imma(int* d, const uint32_t* a,
                                            uint32_t b0, uint32_t b1) {
    asm volatile(
        "mma.sync.aligned.m16n8k32.row.col.s32.s8.s8.s32 "
        "{%0,%1,%2,%3}, {%4,%5,%6,%7}, {%8,%9}, {%0,%1,%2,%3};"
        : "+r"(d[0]), "+r"(d[1]), "+r"(d[2]), "+r"(d[3])
        : "r"(a[0]), "r"(a[1]), "r"(a[2]), "r"(a[3]), "r"(b0), "r"(b1));
}

// ---------------- geometry ----------------------------------------------------
static constexpr int      NCHUNK      = 32;       // 4096 / 128
static constexpr uint32_t TILE_BYTES  = 16384;    // 128 rows x 128 k-bytes
static constexpr uint32_t BTILE_BYTES = 8192;     // 64 rows x 128 k-bytes
static constexpr int      STAGES      = 4;
static constexpr uint32_t OFF_A1      = 16384;
static constexpr uint32_t OFF_B       = 32768;
static constexpr uint32_t STAGE_BYTES = 40960;    // A0 16K + A1 16K + B 8K
static constexpr uint32_t OFF_FULL    = 0;
static constexpr uint32_t OFF_EMPTY   = 64;
static constexpr uint32_t OFF_STAGE   = 1024;
static constexpr uint32_t SMEM_DYN    = OFF_STAGE + STAGES * STAGE_BYTES;  // 164864

// ---------------- merged prologue: pack x (y=0) and sign(W) (y=1) ------------
__global__ void __launch_bounds__(256) prep_kernel(const float* __restrict__ x,
                                                   const float* __restrict__ w) {
    const int row = blockIdx.x;
    const int tid = threadIdx.x;
    const bool is_x = (blockIdx.y == 0);
    const float* src = (is_x ? x : w) + (size_t)row * 4096;

    float4 v[4];
    #pragma unroll
    for (int i = 0; i < 4; i++) v[i] = ((const float4*)src)[tid * 4 + i];

    const uint32_t inrow = (uint32_t)((tid & 7) * 16);
    const uint32_t swzc  = inrow ^ (uint32_t)((row & 7) << 4);
    const size_t off = ((size_t)(row >> 7) * 32 + (size_t)(tid >> 3)) * TILE_BYTES
                     + (size_t)((row & 127) * 128) + swzc;

    if (is_x) {
        float mx = 0.f, sm = 0.f;
        #pragma unroll
        for (int i = 0; i < 4; i++) {
            mx = fmaxf(mx, fmaxf(fmaxf(fabsf(v[i].x), fabsf(v[i].y)),
                                 fmaxf(fabsf(v[i].z), fabsf(v[i].w))));
            sm += (v[i].x + v[i].y) + (v[i].z + v[i].w);
        }
        __shared__ float smax[256], ssum[256];
        smax[tid] = mx; ssum[tid] = sm;
        __syncthreads();
        for (int s = 128; s > 0; s >>= 1) {
            if (tid < s) {
                smax[tid] = fmaxf(smax[tid], smax[tid + s]);
                ssum[tid] += ssum[tid + s];
            }
            __syncthreads();
        }
        const float maxv = smax[0];
        const float inv  = (maxv > 0.f) ? 127.f / maxv : 0.f;

        uint32_t p1[4], p2[4];
        #pragma unroll
        for (int i = 0; i < 4; i++) {
            float e[4] = {v[i].x, v[i].y, v[i].z, v[i].w};
            uint32_t w1 = 0, w2 = 0;
            #pragma unroll
            for (int b = 0; b < 4; b++) {
                float r0 = e[b] * inv;
                int q1 = __float2int_rn(r0);
                int q2 = __float2int_rn((r0 - (float)q1) * 254.f);
                w1 |= (uint32_t)(q1 & 0xff) << (8 * b);
                w2 |= (uint32_t)(q2 & 0xff) << (8 * b);
            }
            p1[i] = w1; p2[i] = w2;
        }
        *(uint4*)((char*)g_a0 + off) = make_uint4(p1[0], p1[1], p1[2], p1[3]);
        *(uint4*)((char*)g_a1 + off) = make_uint4(p2[0], p2[1], p2[2], p2[3]);
        if (tid == 0) {
            g_scale[row]  = (maxv > 0.f) ? maxv / 127.f : 0.f;
            g_rowsum[row] = ssum[0];
        }
    } else {
        uint32_t p[4];
        #pragma unroll
        for (int i = 0; i < 4; i++) {
            float e[4] = {v[i].x, v[i].y, v[i].z, v[i].w};
            uint32_t wq = 0;
            #pragma unroll
            for (int b = 0; b < 4; b++) {
                int q = (e[b] > 0.f) ? 1 : ((e[b] < 0.f) ? -1 : 0);
                wq |= (uint32_t)(q & 0xff) << (8 * b);
            }
            p[i] = wq;
        }
        *(uint4*)((char*)g_b + off) = make_uint4(p[0], p[1], p[2], p[3]);
    }
}

// ---------------- main GEMM ----------------------------------------------------
// grid (64 ntile, 32 mtile), 512 threads. CTA tile 128M x 64N.
// 16 warps: mma 4Mx4N (warp tile 32x16); dp4a per-thread 4x4.
// Warp-parity stagger keeps tensor + fma pipes concurrently fed.
__global__ void __launch_bounds__(512, 1)
gemm_kernel(const float* __restrict__ wscale, const float* __restrict__ wbias,
            float* __restrict__ out) {
    extern __shared__ __align__(1024) char smem[];
    const uint32_t sb = smem_u32(smem);
    const int tid = threadIdx.x;
    const int wid = tid >> 5;
    const int lane = tid & 31;
    const int ntile = blockIdx.x;   // 0..63
    const int mtile = blockIdx.y;   // 0..31

    const char* pa0 = (const char*)g_a0 + (size_t)mtile * (32u * TILE_BYTES);
    const char* pa1 = (const char*)g_a1 + (size_t)mtile * (32u * TILE_BYTES);
    const char* pb  = (const char*)g_b  + (size_t)(ntile >> 1) * (32u * TILE_BYTES)
                    + (size_t)(ntile & 1) * BTILE_BYTES;

    if (tid == 0) {
        #pragma unroll
        for (int s = 0; s < STAGES; s++) {
            MBARRIER_INIT(sb + OFF_FULL  + 8u * s, 1);
            MBARRIER_INIT(sb + OFF_EMPTY + 8u * s, 16);
        }
    }
    __syncthreads();

    if (tid == 0) {
        #pragma unroll
        for (int s = 0; s < STAGES; s++) {
            uint32_t fb = sb + OFF_FULL + 8u * s;
            MBARRIER_EXPECT_TX(fb, STAGE_BYTES);
            uint32_t dst = sb + OFF_STAGE + (uint32_t)s * STAGE_BYTES;
            size_t co = (size_t)s * TILE_BYTES;
            bulk_g2s(dst,          pa0 + co, TILE_BYTES,  fb);
            bulk_g2s(dst + OFF_A1, pa1 + co, TILE_BYTES,  fb);
            bulk_g2s(dst + OFF_B,  pb  + co, BTILE_BYTES, fb);
        }
    }

    // ---- mma (level-1) tiling: 4(M) x 4(N) warps, warp tile 32x16 ----
    const int mw = wid >> 2;          // 0..3
    const int nw = wid & 3;           // 0..3
    const int rA = lane & 15;
    const uint32_t hb = (uint32_t)((lane >> 4) * 16);
    const uint32_t ph_sw = (uint32_t)((rA & 7) << 4);

    uint32_t rowA[2];
    #pragma unroll
    for (int t = 0; t < 2; t++) rowA[t] = (uint32_t)((mw * 32 + t * 16 + rA) * 128);
    const uint32_t rowB = (uint32_t)((nw * 16 + rA) * 128);
    uint32_t colx[4];
    #pragma unroll
    for (int ks = 0; ks < 4; ks++) colx[ks] = ((uint32_t)(ks * 32) + hb) ^ ph_sw;

    // ---- dp4a (level-2) tiling: thread -> rows {g+32i}, cols {h+16j} ----
    const int g = tid & 31;           // 0..31
    const int h = tid >> 5;           // 0..15
    const uint32_t aswz = (uint32_t)((g & 7) * 16);
    const uint32_t bswz = (uint32_t)((h & 7) * 16);

    int acc0[2][2][4];                // level-1 mma accumulators (16 regs)
    int accL[4][4];                   // level-2 dp4a accumulators (16 regs)
    #pragma unroll
    for (int t = 0; t < 2; t++)
        #pragma unroll
        for (int u = 0; u < 2; u++)
            #pragma unroll
            for (int i = 0; i < 4; i++) acc0[t][u][i] = 0;
    #pragma unroll
    for (int i = 0; i < 4; i++)
        #pragma unroll
        for (int j = 0; j < 4; j++) accL[i][j] = 0;

    const bool mma_first = ((wid & 1) == 0);

    for (int ch = 0; ch < NCHUNK; ch++) {
        const int st = ch & 3;
        const int ph = (ch >> 2) & 1;
        MBARRIER_WAIT_PARITY(sb + OFF_FULL + 8u * st, ph);
        const uint32_t SA0 = sb + OFF_STAGE + (uint32_t)st * STAGE_BYTES;
        const uint32_t SB  = SA0 + OFF_B;
        const char* cSA1 = smem + OFF_STAGE + (uint32_t)st * STAGE_BYTES + OFF_A1;
        const char* cSB  = smem + OFF_STAGE + (uint32_t)st * STAGE_BYTES + OFF_B;

        auto do_mma = [&](int ks) {
            uint32_t a0f[2][4], bf[4];
            #pragma unroll
            for (int t = 0; t < 2; t++) ldsm4(a0f[t], SA0 + rowA[t] + colx[ks]);
            ldsm4(bf, SB + rowB + colx[ks]);
            #pragma unroll
            for (int t = 0; t < 2; t++) {
                imma(acc0[t][0], a0f[t], bf[0], bf[2]);
                imma(acc0[t][1], a0f[t], bf[1], bf[3]);
            }
        };
        auto do_dp = [&](int ks) {
            #pragma unroll
            for (int sub = 0; sub < 2; sub++) {
                const uint32_t col = (uint32_t)(ks * 32 + sub * 16);
                int4 a4[4], b4[4];
                #pragma unroll
                for (int i = 0; i < 4; i++)
                    a4[i] = *(const int4*)(cSA1 + (g + 32 * i) * 128 + (col ^ aswz));
                #pragma unroll
                for (int j = 0; j < 4; j++)
                    b4[j] = *(const int4*)(cSB + (h + 16 * j) * 128 + (col ^ bswz));
                #pragma unroll
                for (int i = 0; i < 4; i++)
                    #pragma unroll
                    for (int j = 0; j < 4; j++) {
                        int* a = &accL[i][j];
                        *a = __dp4a(a4[i].x, b4[j].x, *a);
                        *a = __dp4a(a4[i].y, b4[j].y, *a);
                        *a = __dp4a(a4[i].z, b4[j].z, *a);
                        *a = __dp4a(a4[i].w, b4[j].w, *a);
                    }
            }
        };

        if (mma_first) {
            #pragma unroll
            for (int ks = 0; ks < 4; ks++) { do_mma(ks); do_dp(ks); }
        } else {
            #pragma unroll
            for (int ks = 0; ks < 4; ks++) { do_dp(ks); do_mma(ks); }
        }

        if (lane == 0) MBARRIER_ARRIVE(sb + OFF_EMPTY + 8u * st);
        if (tid == 0 && ch + STAGES < NCHUNK) {
            MBARRIER_WAIT_PARITY_RELAXED(sb + OFF_EMPTY + 8u * st, ph);
            uint32_t fb = sb + OFF_FULL + 8u * st;
            MBARRIER_EXPECT_TX(fb, STAGE_BYTES);
            uint32_t dst = sb + OFF_STAGE + (uint32_t)st * STAGE_BYTES;
            size_t co = (size_t)(ch + STAGES) * TILE_BYTES;
            bulk_g2s(dst,          pa0 + co, TILE_BYTES,  fb);
            bulk_g2s(dst + OFF_A1, pa1 + co, TILE_BYTES,  fb);
            bulk_g2s(dst + OFF_B,  pb  + co, BTILE_BYTES, fb);
        }
    }

    // ---------------- epilogue: stage level-2 via SMEM, combine in mma layout --
    __syncthreads();                       // all warps done with stage buffers
    int* sInt = (int*)smem;                // 128 x 68 ints = 34816 B
    #pragma unroll
    for (int i = 0; i < 4; i++)
        #pragma unroll
        for (int j = 0; j < 4; j++)
            sInt[(g + 32 * i) * 68 + (h + 16 * j)] = accL[i][j];
    __syncthreads();

    const float inv254 = 1.f / 254.f;
    const int lg = lane >> 2;           // 0..7
    const int lc = (lane & 3) * 2;      // 0,2,4,6
    const int nlb = nw * 16 + lc;       // local n base
    #pragma unroll
    for (int t = 0; t < 2; t++) {
        #pragma unroll
        for (int half = 0; half < 2; half++) {
            const int ml = mw * 32 + t * 16 + lg + half * 8;   // local m
            const int m  = mtile * 128 + ml;
            const float alpha = g_scale[m];
            const float rs    = g_rowsum[m];
            float* orow = out + (size_t)m * 4096;
            const int i0 = half * 2, i1 = half * 2 + 1;
            #pragma unroll
            for (int u = 0; u < 2; u++) {
                const int nl = nlb + u * 8;
                const int n  = ntile * 64 + nl;
                float v0 = (float)acc0[t][u][i0] + (float)sInt[ml * 68 + nl]     * inv254;
                float v1 = (float)acc0[t][u][i1] + (float)sInt[ml * 68 + nl + 1] * inv254;
                float2 o;
                o.x = __ldg(wscale + n)     * (alpha * v0) + __ldg(wbias + n)     * rs;
                o.y = __ldg(wscale + n + 1) * (alpha * v1) + __ldg(wbias + n + 1) * rs;
                *(float2*)(orow + n) = o;
            }
        }
    }
}

// ---------------- launch --------------------------------------------------------
extern "C" void kernel_launch(void* const* d_in, const int* in_sizes, int n_in,
                              void* d_out, int out_size) {
    (void)in_sizes; (void)n_in; (void)out_size;
    const float* x      = (const float*)d_in[0];   // [2,2048,4096]
    const float* weight = (const float*)d_in[1];   // [4096,4096]
    const float* wscale = (const float*)d_in[2];   // [4096,1]
    const float* wbias  = (const float*)d_in[3];   // [4096,1]
    float* out = (float*)d_out;

    cudaFuncSetAttribute(gemm_kernel, cudaFuncAttributeMaxDynamicSharedMemorySize,
                         (int)SMEM_DYN);

    prep_kernel<<<dim3(4096, 2), 256>>>(x, weight);
    gemm_kernel<<<dim3(64, 32), 512, SMEM_DYN>>>(wscale, wbias, out);
}

// round 14
// speedup vs baseline: 1.3959x; 1.2066x over previous
#include <cuda_runtime.h>
#include <cuda_bf16.h>
#include <cstdint>

// ============================================================================
// BinaryLinearWscales (GB300). Warp-specialized dual-pipe GEMM:
//   warps 0-7  (mma): level-1 q1 x sign -> tensor pipe (R10's proven tiling)
//   warps 8-15 (dp):  level-2 q2 x sign -> fma pipe (broadcast-B layout)
//   x ~= alpha_m * (q1 + q2/254), sign(W) exact in s8.
// Specialization decouples the pipes: a dp warp never issues imma, so
// tensor-queue backpressure can't block fma issue (R13 showed the unified
// warps serialize: tensor 64% + fma 32% = 96% with no overlap).
// ============================================================================

// ---------------- device scratch (pre-swizzled tiled s8) --------------------
__device__ __align__(16384) int8_t g_a0[16777216];   // 16 MB: q1 of x
__device__ __align__(16384) int8_t g_a1[16777216];   // 16 MB: q2 of x
__device__ __align__(16384) int8_t g_b [16777216];   // 16 MB: sign(W)
__device__ float g_scale [4096];
__device__ float g_rowsum[4096];

// ---------------- PTX helpers ------------------------------------------------
static __device__ __forceinline__ uint32_t smem_u32(const void* p) {
    uint32_t a;
    asm("{ .reg .u64 t; cvta.to.shared.u64 t, %1; cvt.u32.u64 %0, t; }" : "=r"(a) : "l"(p));
    return a;
}

#define MBARRIER_INIT(addr, cnt) \
    asm volatile("mbarrier.init.shared.b64 [%0], %1;" :: "r"((uint32_t)(addr)), "r"((uint32_t)(cnt)) : "memory")

#define MBARRIER_EXPECT_TX(addr, bytes) \
    asm volatile("mbarrier.arrive.expect_tx.shared.b64 _, [%0], %1;" :: "r"((uint32_t)(addr)), "r"((uint32_t)(bytes)) : "memory")

#define MBARRIER_ARRIVE(addr) \
    asm volatile("mbarrier.arrive.shared.b64 _, [%0];" :: "r"((uint32_t)(addr)) : "memory")

#define MBARRIER_WAIT_PARITY(mbar_addr, parity) do {                               \
    uint32_t _m = (uint32_t)(mbar_addr); uint32_t _p = (uint32_t)(parity);         \
    uint32_t _d;                                                                    \
    asm volatile("{\n\t.reg .pred p;\n\t"                                           \
        "mbarrier.try_wait.parity.acquire.cta.shared::cta.b64 p, [%1], %2;\n\t"     \
        "selp.b32 %0, 1, 0, p;\n\t}" : "=r"(_d) : "r"(_m), "r"(_p) : "memory");     \
    if (!_d) {                                                                      \
        asm volatile("{\n\t.reg .pred P1;\n\t"                                      \
        "WL_%=:\n\t"                                                                \
        "mbarrier.try_wait.parity.acquire.cta.shared::cta.b64 P1, [%0], %1, 0x989680;\n\t" \
        "@P1 bra.uni WD_%=;\n\t"                                                    \
        "bra.uni WL_%=;\n\t"                                                        \
        "WD_%=:\n\t}" :: "r"(_m), "r"(_p) : "memory");                              \
    }                                                                               \
} while (0)

#define MBARRIER_WAIT_PARITY_RELAXED(mbar_addr, parity) do {                       \
    uint32_t _m = (uint32_t)(mbar_addr); uint32_t _p = (uint32_t)(parity);         \
    uint32_t _d;                                                                    \
    asm volatile("{\n\t.reg .pred p;\n\t"                                           \
        "mbarrier.try_wait.parity.relaxed.cta.shared::cta.b64 p, [%1], %2, 0x989680;\n\t" \
        "selp.b32 %0, 1, 0, p;\n\t}" : "=r"(_d) : "r"(_m), "r"(_p) : "memory");     \
    if (!_d) {                                                                      \
        asm volatile("{\n\t.reg .pred P1;\n\t"                                      \
        "WL_%=:\n\t"                                                                \
        "mbarrier.try_wait.parity.relaxed.cta.shared::cta.b64 P1, [%0], %1, 0x989680;\n\t" \
        "@P1 bra.uni WD_%=;\n\t"                                                    \
        "bra.uni WL_%=;\n\t"                                                        \
        "WD_%=:\n\t}" :: "r"(_m), "r"(_p) : "memory");                              \
    }                                                                               \
} while (0)

static __device__ __forceinline__ void bulk_g2s(uint32_t dst, const void* src,
                                                uint32_t bytes, uint32_t mbar) {
    asm volatile(
        "cp.async.bulk.shared::cluster.global.mbarrier::complete_tx::bytes [%0], [%1], %2, [%3];"
        :: "r"(dst), "l"(src), "r"(bytes), "r"(mbar) : "memory");
}

static __device__ __forceinline__ void ldsm4(uint32_t* r, uint32_t addr) {
    asm volatile("ldmatrix.sync.aligned.m8n8.x4.shared.b16 {%0,%1,%2,%3}, [%4];"
        : "=r"(r[0]), "=r"(r[1]), "=r"(r[2]), "=r"(r[3]) : "r"(addr));
}

static __device__ __forceinline__ void imma(int* d, const uint32_t* a,
                                            uint32_t b0, uint32_t b1) {
    asm volatile(
        "mma.sync.aligned.m16n8k32.row.col.s32.s8.s8.s32 "
        "{%0,%1,%2,%3}, {%4,%5,%6,%7}, {%8,%9}, {%0,%1,%2,%3};"
        : "+r"(d[0]), "+r"(d[1]), "+r"(d[2]), "+r"(d[3])
        : "r"(a[0]), "r"(a[1]), "r"(a[2]), "r"(a[3]), "r"(b0), "r"(b1));
}

static __device__ __forceinline__ void dp4x4(int* acc, const int4& a, const int4& b) {
    *acc = __dp4a(a.x, b.x, *acc);
    *acc = __dp4a(a.y, b.y, *acc);
    *acc = __dp4a(a.z, b.z, *acc);
    *acc = __dp4a(a.w, b.w, *acc);
}

// ---------------- geometry ----------------------------------------------------
static constexpr int      NCHUNK      = 32;       // 4096 / 128
static constexpr uint32_t TILE_BYTES  = 16384;    // 128 rows x 128 k-bytes
static constexpr uint32_t BTILE_BYTES = 8192;     // 64 rows x 128 k-bytes
static constexpr int      STAGES      = 4;
static constexpr uint32_t OFF_A1      = 16384;
static constexpr uint32_t OFF_B       = 32768;
static constexpr uint32_t STAGE_BYTES = 40960;    // A0 16K + A1 16K + B 8K
static constexpr uint32_t OFF_FULL    = 0;
static constexpr uint32_t OFF_EMPTY   = 64;
static constexpr uint32_t OFF_STAGE   = 1024;
static constexpr uint32_t SMEM_DYN    = OFF_STAGE + STAGES * STAGE_BYTES;  // 164864

// ---------------- merged prologue: pack x (y=0) and sign(W) (y=1) ------------
__global__ void __launch_bounds__(256) prep_kernel(const float* __restrict__ x,
                                                   const float* __restrict__ w) {
    const int row = blockIdx.x;
    const int tid = threadIdx.x;
    const bool is_x = (blockIdx.y == 0);
    const float* src = (is_x ? x : w) + (size_t)row * 4096;

    float4 v[4];
    #pragma unroll
    for (int i = 0; i < 4; i++) v[i] = ((const float4*)src)[tid * 4 + i];

    const uint32_t inrow = (uint32_t)((tid & 7) * 16);
    const uint32_t swzc  = inrow ^ (uint32_t)((row & 7) << 4);
    const size_t off = ((size_t)(row >> 7) * 32 + (size_t)(tid >> 3)) * TILE_BYTES
                     + (size_t)((row & 127) * 128) + swzc;

    if (is_x) {
        float mx = 0.f, sm = 0.f;
        #pragma unroll
        for (int i = 0; i < 4; i++) {
            mx = fmaxf(mx, fmaxf(fmaxf(fabsf(v[i].x), fabsf(v[i].y)),
                                 fmaxf(fabsf(v[i].z), fabsf(v[i].w))));
            sm += (v[i].x + v[i].y) + (v[i].z + v[i].w);
        }
        __shared__ float smax[256], ssum[256];
        smax[tid] = mx; ssum[tid] = sm;
        __syncthreads();
        for (int s = 128; s > 0; s >>= 1) {
            if (tid < s) {
                smax[tid] = fmaxf(smax[tid], smax[tid + s]);
                ssum[tid] += ssum[tid + s];
            }
            __syncthreads();
        }
        const float maxv = smax[0];
        const float inv  = (maxv > 0.f) ? 127.f / maxv : 0.f;

        uint32_t p1[4], p2[4];
        #pragma unroll
        for (int i = 0; i < 4; i++) {
            float e[4] = {v[i].x, v[i].y, v[i].z, v[i].w};
            uint32_t w1 = 0, w2 = 0;
            #pragma unroll
            for (int b = 0; b < 4; b++) {
                float r0 = e[b] * inv;
                int q1 = __float2int_rn(r0);
                int q2 = __float2int_rn((r0 - (float)q1) * 254.f);
                w1 |= (uint32_t)(q1 & 0xff) << (8 * b);
                w2 |= (uint32_t)(q2 & 0xff) << (8 * b);
            }
            p1[i] = w1; p2[i] = w2;
        }
        *(uint4*)((char*)g_a0 + off) = make_uint4(p1[0], p1[1], p1[2], p1[3]);
        *(uint4*)((char*)g_a1 + off) = make_uint4(p2[0], p2[1], p2[2], p2[3]);
        if (tid == 0) {
            g_scale[row]  = (maxv > 0.f) ? maxv / 127.f : 0.f;
            g_rowsum[row] = ssum[0];
        }
    } else {
        uint32_t p[4];
        #pragma unroll
        for (int i = 0; i < 4; i++) {
            float e[4] = {v[i].x, v[i].y, v[i].z, v[i].w};
            uint32_t wq = 0;
            #pragma unroll
            for (int b = 0; b < 4; b++) {
                int q = (e[b] > 0.f) ? 1 : ((e[b] < 0.f) ? -1 : 0);
                wq |= (uint32_t)(q & 0xff) << (8 * b);
            }
            p[i] = wq;
        }
        *(uint4*)((char*)g_b + off) = make_uint4(p[0], p[1], p[2], p[3]);
    }
}

// ---------------- main GEMM ----------------------------------------------------
// grid (64 ntile, 32 mtile), 512 threads. CTA tile 128M x 64N.
// warps 0-7: mma level-1, 4Mx2N, warp tile 32x32 (R10-proven).
// warps 8-15: dp4a level-2, warp d -> cols 8d..8d+7; lane -> rows {lane+32i}.
__global__ void __launch_bounds__(512, 1)
gemm_kernel(const float* __restrict__ wscale, const float* __restrict__ wbias,
            float* __restrict__ out) {
    extern __shared__ __align__(1024) char smem[];
    const uint32_t sb = smem_u32(smem);
    const int tid = threadIdx.x;
    const int wid = tid >> 5;
    const int lane = tid & 31;
    const int ntile = blockIdx.x;   // 0..63
    const int mtile = blockIdx.y;   // 0..31

    const char* pa0 = (const char*)g_a0 + (size_t)mtile * (32u * TILE_BYTES);
    const char* pa1 = (const char*)g_a1 + (size_t)mtile * (32u * TILE_BYTES);
    const char* pb  = (const char*)g_b  + (size_t)(ntile >> 1) * (32u * TILE_BYTES)
                    + (size_t)(ntile & 1) * BTILE_BYTES;

    if (tid == 0) {
        #pragma unroll
        for (int s = 0; s < STAGES; s++) {
            MBARRIER_INIT(sb + OFF_FULL  + 8u * s, 1);
            MBARRIER_INIT(sb + OFF_EMPTY + 8u * s, 16);
        }
    }
    __syncthreads();

    if (tid == 0) {
        #pragma unroll
        for (int s = 0; s < STAGES; s++) {
            uint32_t fb = sb + OFF_FULL + 8u * s;
            MBARRIER_EXPECT_TX(fb, STAGE_BYTES);
            uint32_t dst = sb + OFF_STAGE + (uint32_t)s * STAGE_BYTES;
            size_t co = (size_t)s * TILE_BYTES;
            bulk_g2s(dst,          pa0 + co, TILE_BYTES,  fb);
            bulk_g2s(dst + OFF_A1, pa1 + co, TILE_BYTES,  fb);
            bulk_g2s(dst + OFF_B,  pb  + co, BTILE_BYTES, fb);
        }
    }

    if (wid < 8) {
        // ================== MMA warps: level-1, tensor pipe ==================
        const int mw = wid >> 1;          // 0..3
        const int nw = wid & 1;           // 0..1
        const int rA = lane & 15;
        const uint32_t hb = (uint32_t)((lane >> 4) * 16);
        const uint32_t ph_sw = (uint32_t)((rA & 7) << 4);

        uint32_t rowA[2], rowB[2];
        #pragma unroll
        for (int t = 0; t < 2; t++) rowA[t] = (uint32_t)((mw * 32 + t * 16 + rA) * 128);
        #pragma unroll
        for (int j = 0; j < 2; j++) rowB[j] = (uint32_t)((nw * 32 + j * 16 + rA) * 128);
        uint32_t colx[4];
        #pragma unroll
        for (int ks = 0; ks < 4; ks++) colx[ks] = ((uint32_t)(ks * 32) + hb) ^ ph_sw;

        int acc0[2][4][4];                // 32 regs
        #pragma unroll
        for (int t = 0; t < 2; t++)
            #pragma unroll
            for (int u = 0; u < 4; u++)
                #pragma unroll
                for (int i = 0; i < 4; i++) acc0[t][u][i] = 0;

        for (int ch = 0; ch < NCHUNK; ch++) {
            const int st = ch & 3;
            const int ph = (ch >> 2) & 1;
            MBARRIER_WAIT_PARITY(sb + OFF_FULL + 8u * st, ph);
            const uint32_t SA0 = sb + OFF_STAGE + (uint32_t)st * STAGE_BYTES;
            const uint32_t SB  = SA0 + OFF_B;

            #pragma unroll
            for (int ks = 0; ks < 4; ks++) {
                uint32_t a0f[2][4], bf[2][4];
                #pragma unroll
                for (int t = 0; t < 2; t++) ldsm4(a0f[t], SA0 + rowA[t] + colx[ks]);
                #pragma unroll
                for (int j = 0; j < 2; j++) ldsm4(bf[j], SB + rowB[j] + colx[ks]);
                #pragma unroll
                for (int t = 0; t < 2; t++) {
                    #pragma unroll
                    for (int j = 0; j < 2; j++) {
                        imma(acc0[t][2 * j],     a0f[t], bf[j][0], bf[j][2]);
                        imma(acc0[t][2 * j + 1], a0f[t], bf[j][1], bf[j][3]);
                    }
                }
            }
            if (lane == 0) MBARRIER_ARRIVE(sb + OFF_EMPTY + 8u * st);
            if (tid == 0 && ch + STAGES < NCHUNK) {
                MBARRIER_WAIT_PARITY_RELAXED(sb + OFF_EMPTY + 8u * st, ph);
                uint32_t fb = sb + OFF_FULL + 8u * st;
                MBARRIER_EXPECT_TX(fb, STAGE_BYTES);
                uint32_t dst = sb + OFF_STAGE + (uint32_t)st * STAGE_BYTES;
                size_t co = (size_t)(ch + STAGES) * TILE_BYTES;
                bulk_g2s(dst,          pa0 + co, TILE_BYTES,  fb);
                bulk_g2s(dst + OFF_A1, pa1 + co, TILE_BYTES,  fb);
                bulk_g2s(dst + OFF_B,  pb  + co, BTILE_BYTES, fb);
            }
        }

        // ---- epilogue (mma warps combine + store) ----
        __syncthreads();                   // dp warps done; sInt being written
        __syncthreads();                   // sInt complete
        const int* sInt = (const int*)smem;
        const float inv254 = 1.f / 254.f;
        const int lg = lane >> 2;
        const int lc = (lane & 3) * 2;
        const int nlb = nw * 32 + lc;
        #pragma unroll
        for (int t = 0; t < 2; t++) {
            #pragma unroll
            for (int half = 0; half < 2; half++) {
                const int ml = mw * 32 + t * 16 + lg + half * 8;
                const int m  = mtile * 128 + ml;
                const float alpha = g_scale[m];
                const float rs    = g_rowsum[m];
                float* orow = out + (size_t)m * 4096;
                const int i0 = half * 2, i1 = half * 2 + 1;
                #pragma unroll
                for (int u = 0; u < 4; u++) {
                    const int nl = nlb + u * 8;
                    const int n  = ntile * 64 + nl;
                    float v0 = (float)acc0[t][u][i0] + (float)sInt[ml * 68 + nl]     * inv254;
                    float v1 = (float)acc0[t][u][i1] + (float)sInt[ml * 68 + nl + 1] * inv254;
                    float2 o;
                    o.x = __ldg(wscale + n)     * (alpha * v0) + __ldg(wbias + n)     * rs;
                    o.y = __ldg(wscale + n + 1) * (alpha * v1) + __ldg(wbias + n + 1) * rs;
                    *(float2*)(orow + n) = o;
                }
            }
        }
    } else {
        // ================== DP warps: level-2, fma pipe ======================
        const int dwid = wid - 8;          // 0..7: col block 8*dwid..8*dwid+7
        const uint32_t aswz = (uint32_t)((lane & 7) * 16);

        int accL[4][8];                    // 32 regs
        #pragma unroll
        for (int i = 0; i < 4; i++)
            #pragma unroll
            for (int j = 0; j < 8; j++) accL[i][j] = 0;

        for (int ch = 0; ch < NCHUNK; ch++) {
            const int st = ch & 3;
            const int ph = (ch >> 2) & 1;
            MBARRIER_WAIT_PARITY(sb + OFF_FULL + 8u * st, ph);
            const char* cSA1 = smem + OFF_STAGE + (uint32_t)st * STAGE_BYTES + OFF_A1;
            const char* cSB  = smem + OFF_STAGE + (uint32_t)st * STAGE_BYTES + OFF_B;

            #pragma unroll
            for (int ks = 0; ks < 4; ks++) {
                #pragma unroll
                for (int sub = 0; sub < 2; sub++) {
                    const uint32_t col = (uint32_t)(ks * 32 + sub * 16);
                    int4 a4[4];
                    #pragma unroll
                    for (int i = 0; i < 4; i++)
                        a4[i] = *(const int4*)(cSA1 + (lane + 32 * i) * 128 + (col ^ aswz));
                    #pragma unroll
                    for (int j = 0; j < 8; j++) {
                        // b row = dwid*8 + j; (row & 7) == j -> swizzle j*16.
                        const int4 b4 = *(const int4*)(cSB + (dwid * 8 + j) * 128
                                                       + (col ^ (uint32_t)(j * 16)));
                        #pragma unroll
                        for (int i = 0; i < 4; i++) dp4x4(&accL[i][j], a4[i], b4);
                    }
                }
            }
            if (lane == 0) MBARRIER_ARRIVE(sb + OFF_EMPTY + 8u * st);
        }

        // ---- write level-2 sums to SMEM for the mma warps ----
        __syncthreads();                   // everyone done with stage buffers
        int* sInt = (int*)smem;            // 128 x 68 ints
        #pragma unroll
        for (int i = 0; i < 4; i++)
            #pragma unroll
            for (int j = 0; j < 8; j++)
                sInt[(lane + 32 * i) * 68 + (dwid * 8 + j)] = accL[i][j];
        __syncthreads();
    }
}

// ---------------- launch --------------------------------------------------------
extern "C" void kernel_launch(void* const* d_in, const int* in_sizes, int n_in,
                              void* d_out, int out_size) {
    (void)in_sizes; (void)n_in; (void)out_size;
    const float* x      = (const float*)d_in[0];   // [2,2048,4096]
    const float* weight = (const float*)d_in[1];   // [4096,4096]
    const float* wscale = (const float*)d_in[2];   // [4096,1]
    const float* wbias  = (const float*)d_in[3];   // [4096,1]
    float* out = (float*)d_out;

    cudaFuncSetAttribute(gemm_kernel, cudaFuncAttributeMaxDynamicSharedMemorySize,
                         (int)SMEM_DYN);

    prep_kernel<<<dim3(4096, 2), 256>>>(x, weight);
    gemm_kernel<<<dim3(64, 32), 512, SMEM_DYN>>>(wscale, wbias, out);
}